// round 1
// baseline (speedup 1.0000x reference)
#include <cuda_runtime.h>
#include <math.h>

// TropicalAffine: LayerNorm -> max-plus matmul -> max(., bias)
// Inputs (metadata order): x[4096*1024] f32, W[1024*1024] f32, b[1024] f32,
//                          gamma[1024] f32, beta[1024] f32. Output f32 [4096*1024].
//
// Strategy: candidate-pruned exact tropical matmul.
//   xn is standardized (mean 0, var 1 per row) by construction, so the argmax k
//   for out[b,i] almost surely has xn[b,k] large. Select S_b = {k: xn[b,k] > TAU},
//   compute est over S_b only, and certify exactness with the bound
//   excluded-value <= TAU + colmax_W[i]. Rare failures fall back to a full scan
//   of that single output element. Bitwise-exact fp32 semantics.

#define Bn 4096
#define Fn 1024
#define SELCAP 256
#define TAU 1.60f
#define LN_EPS 1e-5f

__device__ float g_xn[Bn * Fn];          // layernorm output (16 MB scratch)
__device__ float g_selval[Bn * SELCAP];  // selected xn values
__device__ int   g_seloff[Bn * SELCAP];  // selected k * Fn (row element offset)
__device__ int   g_cnt[Bn];              // per-row candidate count
__device__ float g_cmax[Fn];             // column max of W

// ---------------------------------------------------------------------------
// Kernel 1: LayerNorm + candidate selection. One block (256 thr) per row.
// ---------------------------------------------------------------------------
__global__ __launch_bounds__(256) void ln_select_kernel(
    const float* __restrict__ x,
    const float* __restrict__ gamma,
    const float* __restrict__ beta)
{
    const int b   = blockIdx.x;
    const int tid = threadIdx.x;

    float4 v = ((const float4*)(x + (size_t)b * Fn))[tid];  // 256*4 = 1024
    float s = v.x + v.y + v.z + v.w;
    float q = v.x * v.x + v.y * v.y + v.z * v.z + v.w * v.w;

    #pragma unroll
    for (int o = 16; o > 0; o >>= 1) {
        s += __shfl_xor_sync(0xFFFFFFFFu, s, o);
        q += __shfl_xor_sync(0xFFFFFFFFu, q, o);
    }

    __shared__ float ws[8], wq[8];
    __shared__ float s_mu, s_rs;
    __shared__ int   s_cnt;

    const int warp = tid >> 5, lane = tid & 31;
    if (tid == 0) s_cnt = 0;
    if (lane == 0) { ws[warp] = s; wq[warp] = q; }
    __syncthreads();

    if (tid == 0) {
        float ts = 0.f, tq = 0.f;
        #pragma unroll
        for (int i = 0; i < 8; i++) { ts += ws[i]; tq += wq[i]; }
        float mu  = ts * (1.0f / Fn);
        float var = tq * (1.0f / Fn) - mu * mu;
        s_mu = mu;
        s_rs = rsqrtf(var + LN_EPS);
    }
    __syncthreads();

    const float mu = s_mu, rs = s_rs;
    float4 g  = ((const float4*)gamma)[tid];
    float4 be = ((const float4*)beta)[tid];

    float xn[4];
    xn[0] = (v.x - mu) * rs * g.x + be.x;
    xn[1] = (v.y - mu) * rs * g.y + be.y;
    xn[2] = (v.z - mu) * rs * g.z + be.z;
    xn[3] = (v.w - mu) * rs * g.w + be.w;

    ((float4*)(g_xn + (size_t)b * Fn))[tid] =
        make_float4(xn[0], xn[1], xn[2], xn[3]);

    const int kbase = tid * 4;
    #pragma unroll
    for (int j = 0; j < 4; j++) {
        if (xn[j] > TAU) {
            int pos = atomicAdd(&s_cnt, 1);
            if (pos < SELCAP) {
                g_selval[b * SELCAP + pos] = xn[j];
                g_seloff[b * SELCAP + pos] = (kbase + j) * Fn;
            }
        }
    }
    __syncthreads();
    if (tid == 0) g_cnt[b] = s_cnt;
}

// ---------------------------------------------------------------------------
// Kernel 2: column max of W (cmax[i] = max_k W[k,i]).
// ---------------------------------------------------------------------------
__global__ __launch_bounds__(256) void colmax_kernel(const float* __restrict__ W)
{
    const int i = blockIdx.x * blockDim.x + threadIdx.x;
    float m = -INFINITY;
    #pragma unroll 8
    for (int k = 0; k < Fn; k++)
        m = fmaxf(m, W[(size_t)k * Fn + i]);
    g_cmax[i] = m;
}

// ---------------------------------------------------------------------------
// Kernel 3: pruned tropical matmul + certificate + fallback + bias.
// One block (128 thr) per row b; each thread owns 8 output columns
// (two dense float4 groups: [tid*4, tid*4+4) and [512+tid*4, 512+tid*4+4)).
// ---------------------------------------------------------------------------
__global__ __launch_bounds__(128) void tropical_kernel(
    const float* __restrict__ W,
    const float* __restrict__ bias,
    float* __restrict__ out)
{
    const int b   = blockIdx.x;
    const int tid = threadIdx.x;

    __shared__ float  s_xn[Fn];
    __shared__ float2 s_ent[SELCAP];  // (xn value, k*Fn as int bits)

    // Stage full xn row (needed only for fallback, cheap to always load).
    #pragma unroll
    for (int j = tid; j < Fn / 4; j += 128)
        ((float4*)s_xn)[j] = ((const float4*)(g_xn + (size_t)b * Fn))[j];

    int cnt = g_cnt[b];
    if (cnt > SELCAP) cnt = 0;  // overflow => force full scan everywhere (safe)

    for (int j = tid; j < cnt; j += 128)
        s_ent[j] = make_float2(g_selval[b * SELCAP + j],
                               __int_as_float(g_seloff[b * SELCAP + j]));
    __syncthreads();

    const int i0 = tid * 4;
    const int i1 = i0 + 512;

    float a[8];
    #pragma unroll
    for (int e = 0; e < 8; e++) a[e] = -INFINITY;

    #pragma unroll 4
    for (int j = 0; j < cnt; j++) {
        float2 ent = s_ent[j];
        const float s = ent.x;
        const float* wr = W + __float_as_int(ent.y);
        float4 w0 = *(const float4*)(wr + i0);
        float4 w1 = *(const float4*)(wr + i1);
        a[0] = fmaxf(a[0], s + w0.x);
        a[1] = fmaxf(a[1], s + w0.y);
        a[2] = fmaxf(a[2], s + w0.z);
        a[3] = fmaxf(a[3], s + w0.w);
        a[4] = fmaxf(a[4], s + w1.x);
        a[5] = fmaxf(a[5], s + w1.y);
        a[6] = fmaxf(a[6], s + w1.z);
        a[7] = fmaxf(a[7], s + w1.w);
    }

    // Exactness certificate: excluded k contribute <= TAU + cmax_i.
    float4 c0 = *(const float4*)(g_cmax + i0);
    float4 c1 = *(const float4*)(g_cmax + i1);
    const float cm[8] = {c0.x, c0.y, c0.z, c0.w, c1.x, c1.y, c1.z, c1.w};
    const int   iv[8] = {i0, i0 + 1, i0 + 2, i0 + 3, i1, i1 + 1, i1 + 2, i1 + 3};

    #pragma unroll
    for (int e = 0; e < 8; e++) {
        if (a[e] < TAU + cm[e]) {
            // Rare exact fallback: full 1024-k scan for this single column.
            float m = -INFINITY;
            const float* wc = W + iv[e];
            for (int k = 0; k < Fn; k++)
                m = fmaxf(m, s_xn[k] + wc[(size_t)k * Fn]);
            a[e] = m;
        }
    }

    // Tropical bias, write out.
    float4 bb0 = *(const float4*)(bias + i0);
    float4 bb1 = *(const float4*)(bias + i1);
    float* orow = out + (size_t)b * Fn;
    *(float4*)(orow + i0) = make_float4(fmaxf(a[0], bb0.x), fmaxf(a[1], bb0.y),
                                        fmaxf(a[2], bb0.z), fmaxf(a[3], bb0.w));
    *(float4*)(orow + i1) = make_float4(fmaxf(a[4], bb1.x), fmaxf(a[5], bb1.y),
                                        fmaxf(a[6], bb1.z), fmaxf(a[7], bb1.w));
}

// ---------------------------------------------------------------------------
extern "C" void kernel_launch(void* const* d_in, const int* in_sizes, int n_in,
                              void* d_out, int out_size)
{
    const float* x     = (const float*)d_in[0];
    const float* W     = (const float*)d_in[1];
    const float* bvec  = (const float*)d_in[2];
    const float* gamma = (const float*)d_in[3];
    const float* beta  = (const float*)d_in[4];
    float* out = (float*)d_out;

    ln_select_kernel<<<Bn, 256>>>(x, gamma, beta);
    colmax_kernel<<<Fn / 256, 256>>>(W);
    tropical_kernel<<<Bn, 128>>>(W, bvec, out);
}

// round 3
// speedup vs baseline: 2.3475x; 2.3475x over previous
#include <cuda_runtime.h>
#include <math.h>

// TropicalAffine: LayerNorm -> max-plus matmul -> max(., bias)
// Candidate-pruned exact tropical matmul, warp-per-row grouped for L1 reuse.
//
// xn is standardized per row, so argmax_k(xn[k]+W[k,i]) almost surely has
// xn[k] > TAU. Select S_b = {k : xn[b,k] > TAU} (bitmask per row), compute
// est over S_b only, certify with: excluded value <= TAU + colmax_W[i]
// (sound in fp32 by monotonicity of round-to-nearest). TAU=1.0 makes the
// certificate fail with prob ~4e-9 -> fallbacks never fire in practice,
// but remain for exactness.
//
// Kernel 3 packs 16 rows per block, one warp per row, sweeping candidates in
// ascending k with a barrier per 32-k word so all 16 warps touch the same W
// rows within an L1-sized window -> W row reads dedupe in L1, cutting L2
// traffic ~2.7x vs flat.

#define Bn 4096
#define Fn 1024
#define Gq 16
#define TAU 1.00f
#define LN_EPS 1e-5f

__device__ float    g_xn[Bn * Fn];        // layernorm output (16 MB scratch)
__device__ unsigned g_rowbits[Bn * 32];   // per-row candidate bitmask (512 KB)
__device__ float    g_cmax[Fn];           // column max of W
__device__ float    g_part[8 * Fn];       // colmax partials

// ---------------------------------------------------------------------------
// Kernel 1: LayerNorm + candidate bitmask. One block (256 thr) per row.
// ---------------------------------------------------------------------------
__global__ __launch_bounds__(256) void ln_select_kernel(
    const float* __restrict__ x,
    const float* __restrict__ gamma,
    const float* __restrict__ beta)
{
    const int b   = blockIdx.x;
    const int tid = threadIdx.x;

    __shared__ float ws[8], wq[8];
    __shared__ float s_mu, s_rs;
    __shared__ unsigned s_bits[32];

    if (tid < 32) s_bits[tid] = 0u;

    float4 v = ((const float4*)(x + (size_t)b * Fn))[tid];  // 256*4 = 1024
    float s = v.x + v.y + v.z + v.w;
    float q = v.x * v.x + v.y * v.y + v.z * v.z + v.w * v.w;

    #pragma unroll
    for (int o = 16; o > 0; o >>= 1) {
        s += __shfl_xor_sync(0xFFFFFFFFu, s, o);
        q += __shfl_xor_sync(0xFFFFFFFFu, q, o);
    }

    const int warp = tid >> 5, lane = tid & 31;
    if (lane == 0) { ws[warp] = s; wq[warp] = q; }
    __syncthreads();

    if (tid == 0) {
        float ts = 0.f, tq = 0.f;
        #pragma unroll
        for (int i = 0; i < 8; i++) { ts += ws[i]; tq += wq[i]; }
        float mu  = ts * (1.0f / Fn);
        float var = tq * (1.0f / Fn) - mu * mu;
        s_mu = mu;
        s_rs = rsqrtf(var + LN_EPS);
    }
    __syncthreads();

    const float mu = s_mu, rs = s_rs;
    float4 g  = ((const float4*)gamma)[tid];
    float4 be = ((const float4*)beta)[tid];

    float xn[4];
    xn[0] = (v.x - mu) * rs * g.x + be.x;
    xn[1] = (v.y - mu) * rs * g.y + be.y;
    xn[2] = (v.z - mu) * rs * g.z + be.z;
    xn[3] = (v.w - mu) * rs * g.w + be.w;

    ((float4*)(g_xn + (size_t)b * Fn))[tid] =
        make_float4(xn[0], xn[1], xn[2], xn[3]);

    // Thread handles k = 4*tid .. 4*tid+3, all inside word tid>>3.
    unsigned bits = 0u;
    #pragma unroll
    for (int j = 0; j < 4; j++)
        if (xn[j] > TAU) bits |= (1u << j);
    if (bits)
        atomicOr(&s_bits[tid >> 3], bits << ((tid & 7) * 4));
    __syncthreads();

    if (tid < 32) g_rowbits[b * 32 + tid] = s_bits[tid];
}

// ---------------------------------------------------------------------------
// Kernel 2a/2b: column max of W, two-stage for parallelism.
// ---------------------------------------------------------------------------
__global__ __launch_bounds__(256) void colmax_a(const float* __restrict__ W)
{
    const int kc = blockIdx.x >> 2;                      // 0..7 (k chunk)
    const int i  = (blockIdx.x & 3) * 256 + threadIdx.x; // column
    float m = -INFINITY;
    const int k0 = kc * 128;
    #pragma unroll 8
    for (int k = k0; k < k0 + 128; k++)
        m = fmaxf(m, W[(size_t)k * Fn + i]);
    g_part[kc * Fn + i] = m;
}

__global__ __launch_bounds__(256) void colmax_b()
{
    const int i = blockIdx.x * 256 + threadIdx.x;
    float m = -INFINITY;
    #pragma unroll
    for (int j = 0; j < 8; j++)
        m = fmaxf(m, g_part[j * Fn + i]);
    g_cmax[i] = m;
}

// ---------------------------------------------------------------------------
// Kernel 3: grouped pruned tropical matmul. 16 rows/block, warp w = row w.
// Each thread owns 32 output columns: i = c*128 + lane*4 + e, c=0..7, e=0..3.
// Accumulators fully register-resident with static indexing.
// ---------------------------------------------------------------------------
__global__ __launch_bounds__(512) void tropical_kernel(
    const float* __restrict__ W,
    const float* __restrict__ bias,
    float* __restrict__ out)
{
    const int g    = blockIdx.x;           // group of 16 rows
    const int tid  = threadIdx.x;
    const int wid  = tid >> 5;             // row within group
    const int lane = tid & 31;
    const int b    = g * Gq + wid;

    __shared__ float    s_xn[Gq][Fn];      // 64 KB
    __shared__ unsigned s_bits[Gq * 32];   // 2 KB

    // Stage xn for all 16 rows + bitmasks.
    #pragma unroll
    for (int j = tid; j < Gq * Fn / 4; j += 512)
        ((float4*)s_xn)[j] = ((const float4*)(g_xn + (size_t)g * Gq * Fn))[j];
    for (int j = tid; j < Gq * 32; j += 512)
        s_bits[j] = g_rowbits[g * Gq * 32 + j];
    __syncthreads();

    float a[8][4];
    #pragma unroll
    for (int c = 0; c < 8; c++)
        #pragma unroll
        for (int e = 0; e < 4; e++) a[c][e] = -INFINITY;

    // Sweep candidate k in ascending order; barrier per 32-k word keeps the
    // 16 warps' W-row accesses inside an L1-sized window (~24 rows).
    for (int w = 0; w < 32; w++) {
        unsigned m = s_bits[wid * 32 + w];
        while (m) {
            const int bit = __ffs(m) - 1;
            m &= m - 1;
            const int k = w * 32 + bit;
            const float sv = s_xn[wid][k];
            const float4* wr = (const float4*)(W + (size_t)k * Fn) + lane;
            #pragma unroll
            for (int c = 0; c < 8; c++) {
                float4 wv = wr[c * 32];
                a[c][0] = fmaxf(a[c][0], sv + wv.x);
                a[c][1] = fmaxf(a[c][1], sv + wv.y);
                a[c][2] = fmaxf(a[c][2], sv + wv.z);
                a[c][3] = fmaxf(a[c][3], sv + wv.w);
            }
        }
        __syncthreads();
    }

    // Certificate + (near-impossible) exact fallback + tropical bias + store.
    float* orow = out + (size_t)b * Fn;
    #pragma unroll
    for (int c = 0; c < 8; c++) {
        const int i = c * 128 + lane * 4;
        float4 cm = *(const float4*)(g_cmax + i);
        const float th[4] = {TAU + cm.x, TAU + cm.y, TAU + cm.z, TAU + cm.w};
        #pragma unroll
        for (int e = 0; e < 4; e++) {
            if (a[c][e] < th[e]) {
                float mfull = -INFINITY;
                const float* wc = W + (i + e);
                for (int k = 0; k < Fn; k++)
                    mfull = fmaxf(mfull, s_xn[wid][k] + wc[(size_t)k * Fn]);
                a[c][e] = mfull;
            }
        }
        float4 bb = *(const float4*)(bias + i);
        *(float4*)(orow + i) = make_float4(fmaxf(a[c][0], bb.x),
                                           fmaxf(a[c][1], bb.y),
                                           fmaxf(a[c][2], bb.z),
                                           fmaxf(a[c][3], bb.w));
    }
}

// ---------------------------------------------------------------------------
extern "C" void kernel_launch(void* const* d_in, const int* in_sizes, int n_in,
                              void* d_out, int out_size)
{
    const float* x     = (const float*)d_in[0];
    const float* W     = (const float*)d_in[1];
    const float* bvec  = (const float*)d_in[2];
    const float* gamma = (const float*)d_in[3];
    const float* beta  = (const float*)d_in[4];
    float* out = (float*)d_out;

    ln_select_kernel<<<Bn, 256>>>(x, gamma, beta);
    colmax_a<<<32, 256>>>(x ? (const float*)d_in[1] : W);  // W
    colmax_b<<<4, 256>>>();
    tropical_kernel<<<Bn / Gq, 512>>>(W, bvec, out);
}